// round 1
// baseline (speedup 1.0000x reference)
#include <cuda_runtime.h>

// PhysicsEngine: B=8, NL=128, NP=8192 pairwise soft-core energy -> 3 scalars/batch.
// Pass 1: grid (64 chunks, 8 batches), block 128 threads (1 thread = 1 ligand),
//         inner loop over 128 SMEM-staged protein atoms. Deterministic block partials.
// Pass 2: tiny finalize kernel combines partials and writes 24 outputs
//         [e_raw(8), e_hard_final(8), log_energy(8)].

#define NB 8
#define NL 128
#define NP 8192
#define CHUNK 128
#define NCHUNK (NP / CHUNK)

// scratch partials: [batch][chunk][5]  (main, diff, hsa, pauli, ghost)
__device__ float g_part[NB * NCHUNK * 5];

__global__ __launch_bounds__(CHUNK) void pe_pair_kernel(
    const float* __restrict__ pos_L, const float* __restrict__ pos_P,
    const float* __restrict__ q_L,   const float* __restrict__ q_P,
    const float* __restrict__ x_L,   const float* __restrict__ x_P,
    const float* __restrict__ vdw_radii, const float* __restrict__ epsilon)
{
    const int c = blockIdx.x;            // protein chunk
    const int b = blockIdx.y;            // batch
    const int l = threadIdx.x;           // ligand index (0..127)

    // ---- per-ligand derived quantities (registers) ----
    const float* xl = x_L + ((size_t)b * NL + l) * 9;
    float radL = 0.f, epsd = 0.f;
#pragma unroll
    for (int k = 0; k < 9; k++) {
        float x = xl[k];
        radL = fmaf(x, vdw_radii[k], radL);
        epsd = fmaf(x, epsilon[k],   epsd);
    }
    epsd = fmaxf(epsd, 0.f);
    const float c4  = 4.f * sqrtf(fmaf(epsd, 0.15f, 1e-8f));  // 4*eps_ij
    const float lx  = pos_L[((size_t)b * NL + l) * 3 + 0];
    const float ly  = pos_L[((size_t)b * NL + l) * 3 + 1];
    const float lz  = pos_L[((size_t)b * NL + l) * 3 + 2];
    const float ql  = q_L[b * NL + l];
    const float xl0 = xl[0];

    // ---- stage protein chunk into SMEM ----
    __shared__ float spx[CHUNK], spy[CHUNK], spz[CHUNK],
                     sq[CHUNK], srad[CHUNK], sx0[CHUNK];
    {
        const int p = c * CHUNK + threadIdx.x;
        const float* xp = x_P + ((size_t)b * NP + p) * 4;
        float x0 = xp[0], x1 = xp[1], x2 = xp[2], x3 = xp[3];
        srad[threadIdx.x] = fmaf(x0, 1.7f, fmaf(x1, 1.55f, fmaf(x2, 1.52f, x3 * 1.8f)));
        sx0[threadIdx.x]  = x0;
        spx[threadIdx.x]  = pos_P[((size_t)b * NP + p) * 3 + 0];
        spy[threadIdx.x]  = pos_P[((size_t)b * NP + p) * 3 + 1];
        spz[threadIdx.x]  = pos_P[((size_t)b * NP + p) * 3 + 2];
        sq[threadIdx.x]   = q_P[b * NP + p];
    }
    __syncthreads();

    float s_main = 0.f, s_diff = 0.f, s_hsa = 0.f, s_pauli = 0.f, s_ghost = 0.f;

#pragma unroll 4
    for (int j = 0; j < CHUNK; j++) {
        const float dx = lx - spx[j];
        const float dy = ly - spy[j];
        const float dz = lz - spz[j];
        const float dsq = fmaf(dx, dx, fmaf(dy, dy, dz * dz));
        // Warp-coherent far cutoff: beyond 26 A every term is < 1e-11
        // (dist_mask = sigmoid(2*(12-d)) <= 6.9e-13; pauli needs d < 0.6*sigma <= 14.8;
        //  ghost needs d < 0.5). Lanes are clustered ligands -> coherent branch.
        if (__any_sync(0xffffffffu, dsq < 676.f)) {
            const float t    = dsq + 1e-8f;
            const float invd = rsqrtf(t);
            const float dist = t * invd;                     // sqrt(dsq + 1e-8)

            const float sigma = radL + srad[j];
            const float ssq   = fmaf(sigma, sigma, t);       // dsq + sigma^2 + 1e-8
            const float invs  = rsqrtf(ssq);                 // 1/soft_dist

            const float e_elec = 83.015f * ql * sq[j] * invs;   // 332.06/(4*soft)

            // ratio = sigma/soft_dist <= 1 always (min(.,5) never binds)
            const float ratio = sigma * invs;
            const float r2 = ratio * ratio;
            const float r6 = r2 * r2 * r2;
            const float evr = c4 * (r6 * r6 - r6);           // e_vdw_raw in [-0.52, 0]
            // softplus(evr+10)-10 = evr + log1p(exp(-(evr+10))) ~= evr + exp(-(evr+10));
            // upper soft clamp at 500 and clip(-10,500) provably never bind.
            const float ex = __expf(-(evr + 10.f));

            // dist_mask = sigmoid((12-d)*2)
            const float em   = __expf(fmaf(2.f, dist, -24.f));
            const float mask = __fdividef(1.f, 1.f + em);

            s_main = fmaf(e_elec + evr + ex, mask, s_main);  // (elec + vdw_grad)*mask
            s_diff = fmaf(ex, mask, s_diff);                 // main - log term

            // hsa_term = 1/(1+(d/4)^4)
            const float dq4 = dist * 0.25f;
            const float d2  = dq4 * dq4;
            const float hsa = __fdividef(1.f, fmaf(d2, d2, 1.f));
            s_hsa = fmaf(xl0 * sx0[j] * hsa, mask, s_hsa);

            const float ov = fmaxf(fmaf(sigma, 0.6f, -dist), 0.f);
            s_pauli = fmaf(ov, ov, s_pauli);
            const float gh = fmaxf(0.5f - dist, 0.f);
            s_ghost = fmaf(gh, gh, s_ghost);
        }
    }

    // ---- deterministic block reduction ----
    float v[5] = {s_main, s_diff, s_hsa, s_pauli, s_ghost};
#pragma unroll
    for (int k = 0; k < 5; k++) {
#pragma unroll
        for (int off = 16; off > 0; off >>= 1)
            v[k] += __shfl_down_sync(0xffffffffu, v[k], off);
    }
    __shared__ float wred[4][5];
    const int wid = threadIdx.x >> 5, lane = threadIdx.x & 31;
    if (lane == 0) {
#pragma unroll
        for (int k = 0; k < 5; k++) wred[wid][k] = v[k];
    }
    __syncthreads();
    if (threadIdx.x == 0) {
#pragma unroll
        for (int k = 0; k < 5; k++) {
            float s = wred[0][k] + wred[1][k] + wred[2][k] + wred[3][k];
            g_part[(b * NCHUNK + c) * 5 + k] = s;
        }
    }
}

__global__ __launch_bounds__(256) void pe_finalize_kernel(float* __restrict__ out)
{
    const int w = threadIdx.x >> 5;     // batch
    const int lane = threadIdx.x & 31;
    if (w >= NB) return;

    float s[5];
#pragma unroll
    for (int k = 0; k < 5; k++) {
        s[k] = g_part[(w * NCHUNK + lane) * 5 + k]
             + g_part[(w * NCHUNK + lane + 32) * 5 + k];
#pragma unroll
        for (int off = 16; off > 0; off >>= 1)
            s[k] += __shfl_down_sync(0xffffffffu, s[k], off);
    }

    if (lane == 0) {
        const float s_main = s[0], s_diff = s[1], s_hsa = s[2],
                    s_pauli = s[3], s_ghost = s[4];
        const float e_hsa5  = -2.5f * s_hsa;                      // 5 * (-0.5 * s_hsa)
        const float e_pauli = 11.920292202211755f * s_pauli;      // 100*sigmoid(-2)
        const float e_ghost = 500.f * s_ghost;

        const float e_raw = s_main + e_hsa5 + e_pauli + e_ghost;

        float log_soft = (s_main - s_diff) + e_hsa5;
        float e_soft_final = fminf(fmaxf(log_soft, -500.f), 5000.f);
        float e_hard = fminf(e_pauli + e_ghost, 10000.f);
        float log_energy = fminf(e_soft_final + e_hard, 1000000.f);

        out[w]      = e_raw;
        out[8 + w]  = e_hard;
        out[16 + w] = log_energy;
    }
}

extern "C" void kernel_launch(void* const* d_in, const int* in_sizes, int n_in,
                              void* d_out, int out_size)
{
    const float* pos_L = (const float*)d_in[0];
    const float* pos_P = (const float*)d_in[1];
    const float* q_L   = (const float*)d_in[2];
    const float* q_P   = (const float*)d_in[3];
    const float* x_L   = (const float*)d_in[4];
    const float* x_P   = (const float*)d_in[5];
    const float* vdw   = (const float*)d_in[6];
    const float* eps   = (const float*)d_in[7];

    dim3 grid(NCHUNK, NB);
    pe_pair_kernel<<<grid, CHUNK>>>(pos_L, pos_P, q_L, q_P, x_L, x_P, vdw, eps);
    pe_finalize_kernel<<<1, 256>>>((float*)d_out);
}